// round 4
// baseline (speedup 1.0000x reference)
#include <cuda_runtime.h>
#include <cstdint>

// Problem shapes (fixed)
#define B_  8
#define C_  64
#define N_  2000
#define T_  12
#define E_  64000
#define HID_ 32

// Scratch
__device__ float g_M1[C_ * C_];           // M1[cin*64 + cout]
__device__ float g_M2[C_ * C_];
// Blocked tables: A_blk[b][g][n][8]  (g = channel-group of 8, 8 groups)
// float4 index: ((b*8+g)*2000 + n)*2 + h,  h in {0,1}
__device__ float g_A[B_ * N_ * C_];       // includes conv_b
__device__ float g_Bv[B_ * N_ * C_];

// ---------------------------------------------------------------------------
// Kernel 1: fold W3/W4 with conv_w and scales into 64x64 matrices.
// ---------------------------------------------------------------------------
__global__ __launch_bounds__(256) void fold_M_kernel(const float* __restrict__ W3,
                                                     const float* __restrict__ W4,
                                                     const float* __restrict__ cw,
                                                     const float* __restrict__ s1p,
                                                     const float* __restrict__ s2p) {
    __shared__ float cwt[64 * 65];   // cwt[h][cout], padded
    const int tid = threadIdx.x;

    for (int i = tid; i < 64 * 64; i += 256) {
        int cout = i >> 6;
        int h = i & 63;
        cwt[h * 65 + cout] = cw[i];
    }

    const int cout = tid & 63;
    const int cin = blockIdx.x * 4 + (tid >> 6);

    float w3r[HID_], w4r[HID_];
    const float4* p3 = reinterpret_cast<const float4*>(W3 + cin * HID_);
    const float4* p4 = reinterpret_cast<const float4*>(W4 + cin * HID_);
#pragma unroll
    for (int q = 0; q < 8; q++) {
        float4 v3 = p3[q], v4 = p4[q];
        w3r[q * 4 + 0] = v3.x; w3r[q * 4 + 1] = v3.y; w3r[q * 4 + 2] = v3.z; w3r[q * 4 + 3] = v3.w;
        w4r[q * 4 + 0] = v4.x; w4r[q * 4 + 1] = v4.y; w4r[q * 4 + 2] = v4.z; w4r[q * 4 + 3] = v4.w;
    }
    __syncthreads();

    float a = 0.f, b = 0.f;
#pragma unroll
    for (int h = 0; h < HID_; h++) {
        a = fmaf(w3r[h], cwt[h * 65 + cout], a);
        b = fmaf(w4r[h], cwt[(h + HID_) * 65 + cout], b);
    }
    g_M1[cin * 64 + cout] = a * s1p[0];
    g_M2[cin * 64 + cout] = b * s2p[0];
}

// ---------------------------------------------------------------------------
// Kernel 2: time reduction + 64x64 projection, 64-n tile per block.
// Writes the BLOCKED table layout.
// ---------------------------------------------------------------------------
__global__ __launch_bounds__(256) void stage_AB_kernel(const float* __restrict__ x,
                                                       const float* __restrict__ conv_b) {
    __shared__ float4 sM1[64 * 16];    // [c][co/4]   16 KB
    __shared__ float4 sM2[64 * 16];    // 16 KB
    __shared__ float4 slt4[64 * 16];   // [c][n/4]    16 KB
    __shared__ float4 srt4[64 * 16];   // 16 KB
    float* sM1f = reinterpret_cast<float*>(sM1);
    float* sM2f = reinterpret_cast<float*>(sM2);
    float* slt = reinterpret_cast<float*>(slt4);
    float* srt = reinterpret_cast<float*>(srt4);

    const int tid = threadIdx.x;
    const int b = blockIdx.y;
    const int n0 = blockIdx.x * 64;

    for (int i = tid; i < 64 * 64; i += 256) {
        sM1f[i] = g_M1[i];
        sM2f[i] = g_M2[i];
    }

    // Phase 1: time reduction. 64c x 64n pairs, 16 per thread.
#pragma unroll
    for (int k = 0; k < 16; k++) {
        int p = tid + 256 * k;
        int c = p >> 6;
        int nl = p & 63;
        int n = n0 + nl;
        float lt = 0.f, s = 0.f;
        if (n < N_) {
            const float4* px = reinterpret_cast<const float4*>(
                x + ((size_t)(b * C_ + c) * N_ + n) * T_);
            float4 v0 = px[0], v1 = px[1], v2 = px[2];
            float xv[12] = {v0.x, v0.y, v0.z, v0.w,
                            v1.x, v1.y, v1.z, v1.w,
                            v2.x, v2.y, v2.z, v2.w};
#pragma unroll
            for (int t = 0; t < T_; t++) {
                lt = fmaf(xv[t], (float)t * (1.0f / 11.0f), lt);
                s += xv[t];
            }
        }
        slt[c * 64 + nl] = lt;
        srt[c * 64 + nl] = s - lt;    // t_dn = 1 - t_up
    }
    __syncthreads();

    // Phase 2: 4n x 4co x {M1,M2} register tiles.
    const int cg = tid & 15;          // co group (co0 = cg*4)
    const int ng = tid >> 4;          // n group  (n_l0 = ng*4)

    float4 a0 = {0,0,0,0}, a1 = {0,0,0,0}, a2 = {0,0,0,0}, a3 = {0,0,0,0};
    float4 b0 = {0,0,0,0}, b1 = {0,0,0,0}, b2 = {0,0,0,0}, b3 = {0,0,0,0};

#pragma unroll 16
    for (int c = 0; c < 64; c++) {
        float4 m1 = sM1[c * 16 + cg];
        float4 m2 = sM2[c * 16 + cg];
        float4 l = slt4[c * 16 + ng];
        float4 r = srt4[c * 16 + ng];

        a0.x = fmaf(l.x, m1.x, a0.x); a0.y = fmaf(l.x, m1.y, a0.y);
        a0.z = fmaf(l.x, m1.z, a0.z); a0.w = fmaf(l.x, m1.w, a0.w);
        a1.x = fmaf(l.y, m1.x, a1.x); a1.y = fmaf(l.y, m1.y, a1.y);
        a1.z = fmaf(l.y, m1.z, a1.z); a1.w = fmaf(l.y, m1.w, a1.w);
        a2.x = fmaf(l.z, m1.x, a2.x); a2.y = fmaf(l.z, m1.y, a2.y);
        a2.z = fmaf(l.z, m1.z, a2.z); a2.w = fmaf(l.z, m1.w, a2.w);
        a3.x = fmaf(l.w, m1.x, a3.x); a3.y = fmaf(l.w, m1.y, a3.y);
        a3.z = fmaf(l.w, m1.z, a3.z); a3.w = fmaf(l.w, m1.w, a3.w);

        b0.x = fmaf(r.x, m2.x, b0.x); b0.y = fmaf(r.x, m2.y, b0.y);
        b0.z = fmaf(r.x, m2.z, b0.z); b0.w = fmaf(r.x, m2.w, b0.w);
        b1.x = fmaf(r.y, m2.x, b1.x); b1.y = fmaf(r.y, m2.y, b1.y);
        b1.z = fmaf(r.y, m2.z, b1.z); b1.w = fmaf(r.y, m2.w, b1.w);
        b2.x = fmaf(r.z, m2.x, b2.x); b2.y = fmaf(r.z, m2.y, b2.y);
        b2.z = fmaf(r.z, m2.z, b2.z); b2.w = fmaf(r.z, m2.w, b2.w);
        b3.x = fmaf(r.w, m2.x, b3.x); b3.y = fmaf(r.w, m2.y, b3.y);
        b3.z = fmaf(r.w, m2.z, b3.z); b3.w = fmaf(r.w, m2.w, b3.w);
    }

    float4 cbv = reinterpret_cast<const float4*>(conv_b)[cg];
    float4* gA4 = reinterpret_cast<float4*>(g_A);
    float4* gB4 = reinterpret_cast<float4*>(g_Bv);

    const int g = cg >> 1;            // channel-group of 8
    const int h = cg & 1;             // half within group

    float4 av[4] = {a0, a1, a2, a3};
    float4 bv[4] = {b0, b1, b2, b3};
#pragma unroll
    for (int i = 0; i < 4; i++) {
        int n = n0 + ng * 4 + i;
        if (n < N_) {
            size_t o = ((size_t)(b * 8 + g) * N_ + n) * 2 + h;   // blocked layout
            float4 aa = av[i];
            aa.x += cbv.x; aa.y += cbv.y; aa.z += cbv.z; aa.w += cbv.w;
            gA4[o] = aa;
            gB4[o] = bv[i];
        }
    }
}

// ---------------------------------------------------------------------------
// Kernel 3: gather+add with L1-resident blocked tables.
// Grid: (edge-chunk, g, b). Each block owns the 128 KB (A,Bv) slice for
// (b,g) in L1 and streams 16000 edges through it.
// ---------------------------------------------------------------------------
#define ECHUNK 16000
__global__ __launch_bounds__(256) void gather_add_kernel(const int* __restrict__ idx,
                                                         const int* __restrict__ idy,
                                                         float4* __restrict__ out) {
    const int ec = blockIdx.x;        // 0..3
    const int g  = blockIdx.y;        // 0..7
    const int b  = blockIdx.z;        // 0..7
    const int tid = threadIdx.x;

    const float4* __restrict__ Ab =
        reinterpret_cast<const float4*>(g_A) + (size_t)(b * 8 + g) * N_ * 2;
    const float4* __restrict__ Bb =
        reinterpret_cast<const float4*>(g_Bv) + (size_t)(b * 8 + g) * N_ * 2;

    const int e0 = ec * ECHUNK;
    for (int i = tid; i < ECHUNK; i += 256) {
        int e = e0 + i;
        int n1 = idx[e];
        int n2 = idy[e];
        float4 a0 = __ldg(Ab + n1 * 2);
        float4 a1 = __ldg(Ab + n1 * 2 + 1);
        float4 v0 = __ldg(Bb + n2 * 2);
        float4 v1 = __ldg(Bb + n2 * 2 + 1);
        size_t o = ((size_t)b * E_ + e) * 16 + g * 2;
        out[o]     = make_float4(a0.x + v0.x, a0.y + v0.y, a0.z + v0.z, a0.w + v0.w);
        out[o + 1] = make_float4(a1.x + v1.x, a1.y + v1.y, a1.z + v1.z, a1.w + v1.w);
    }
}

// ---------------------------------------------------------------------------
// Launch. Inputs: x, idx, idy, W1_scale, W2_scale, W3, W4, conv_w, conv_b
// ---------------------------------------------------------------------------
extern "C" void kernel_launch(void* const* d_in, const int* in_sizes, int n_in,
                              void* d_out, int out_size) {
    const float* x   = (const float*)d_in[0];
    const int* idx   = (const int*)d_in[1];
    const int* idy   = (const int*)d_in[2];
    const float* s1  = (const float*)d_in[3];
    const float* s2  = (const float*)d_in[4];
    const float* W3  = (const float*)d_in[5];
    const float* W4  = (const float*)d_in[6];
    const float* cw  = (const float*)d_in[7];
    const float* cb  = (const float*)d_in[8];
    float4* out = (float4*)d_out;

    fold_M_kernel<<<16, 256>>>(W3, W4, cw, s1, s2);

    dim3 grd2((N_ + 63) / 64, B_);
    stage_AB_kernel<<<grd2, 256>>>(x, cb);

    dim3 grd3(E_ / ECHUNK, 8, B_);    // (4, 8, 8) = 256 blocks
    gather_add_kernel<<<grd3, 256>>>(idx, idy, out);
}

// round 5
// speedup vs baseline: 1.3009x; 1.3009x over previous
#include <cuda_runtime.h>
#include <cstdint>

// Problem shapes (fixed)
#define B_  8
#define C_  64
#define N_  2000
#define T_  12
#define E_  64000
#define HID_ 32

// Scratch
__device__ float g_M1[C_ * C_];           // M1[cin*64 + cout]
__device__ float g_M2[C_ * C_];
// Blocked tables: A_blk[b][g][n][8]  (g = channel-group of 8, 8 groups)
// float4 index: ((b*8+g)*2000 + n)*2 + h,  h in {0,1}
__device__ float g_A[B_ * N_ * C_];       // includes conv_b
__device__ float g_Bv[B_ * N_ * C_];

// ---------------------------------------------------------------------------
// Kernel 1: fold W3/W4 with conv_w and scales into 64x64 matrices.
// ---------------------------------------------------------------------------
__global__ __launch_bounds__(256) void fold_M_kernel(const float* __restrict__ W3,
                                                     const float* __restrict__ W4,
                                                     const float* __restrict__ cw,
                                                     const float* __restrict__ s1p,
                                                     const float* __restrict__ s2p) {
    __shared__ float cwt[64 * 65];   // cwt[h][cout], padded
    const int tid = threadIdx.x;

    for (int i = tid; i < 64 * 64; i += 256) {
        int cout = i >> 6;
        int h = i & 63;
        cwt[h * 65 + cout] = cw[i];
    }

    const int cout = tid & 63;
    const int cin = blockIdx.x * 4 + (tid >> 6);

    float w3r[HID_], w4r[HID_];
    const float4* p3 = reinterpret_cast<const float4*>(W3 + cin * HID_);
    const float4* p4 = reinterpret_cast<const float4*>(W4 + cin * HID_);
#pragma unroll
    for (int q = 0; q < 8; q++) {
        float4 v3 = p3[q], v4 = p4[q];
        w3r[q * 4 + 0] = v3.x; w3r[q * 4 + 1] = v3.y; w3r[q * 4 + 2] = v3.z; w3r[q * 4 + 3] = v3.w;
        w4r[q * 4 + 0] = v4.x; w4r[q * 4 + 1] = v4.y; w4r[q * 4 + 2] = v4.z; w4r[q * 4 + 3] = v4.w;
    }
    __syncthreads();

    float a = 0.f, b = 0.f;
#pragma unroll
    for (int h = 0; h < HID_; h++) {
        a = fmaf(w3r[h], cwt[h * 65 + cout], a);
        b = fmaf(w4r[h], cwt[(h + HID_) * 65 + cout], b);
    }
    g_M1[cin * 64 + cout] = a * s1p[0];
    g_M2[cin * 64 + cout] = b * s2p[0];
}

// ---------------------------------------------------------------------------
// Kernel 2: time reduction + 64x64 projection, 64-n tile per block.
// Writes the BLOCKED table layout.
// ---------------------------------------------------------------------------
__global__ __launch_bounds__(256) void stage_AB_kernel(const float* __restrict__ x,
                                                       const float* __restrict__ conv_b) {
    __shared__ float4 sM1[64 * 16];    // [c][co/4]   16 KB
    __shared__ float4 sM2[64 * 16];    // 16 KB
    __shared__ float4 slt4[64 * 16];   // [c][n/4]    16 KB
    __shared__ float4 srt4[64 * 16];   // 16 KB
    float* sM1f = reinterpret_cast<float*>(sM1);
    float* sM2f = reinterpret_cast<float*>(sM2);
    float* slt = reinterpret_cast<float*>(slt4);
    float* srt = reinterpret_cast<float*>(srt4);

    const int tid = threadIdx.x;
    const int b = blockIdx.y;
    const int n0 = blockIdx.x * 64;

    for (int i = tid; i < 64 * 64; i += 256) {
        sM1f[i] = g_M1[i];
        sM2f[i] = g_M2[i];
    }

    // Phase 1: time reduction. 64c x 64n pairs, 16 per thread.
#pragma unroll
    for (int k = 0; k < 16; k++) {
        int p = tid + 256 * k;
        int c = p >> 6;
        int nl = p & 63;
        int n = n0 + nl;
        float lt = 0.f, s = 0.f;
        if (n < N_) {
            const float4* px = reinterpret_cast<const float4*>(
                x + ((size_t)(b * C_ + c) * N_ + n) * T_);
            float4 v0 = px[0], v1 = px[1], v2 = px[2];
            float xv[12] = {v0.x, v0.y, v0.z, v0.w,
                            v1.x, v1.y, v1.z, v1.w,
                            v2.x, v2.y, v2.z, v2.w};
#pragma unroll
            for (int t = 0; t < T_; t++) {
                lt = fmaf(xv[t], (float)t * (1.0f / 11.0f), lt);
                s += xv[t];
            }
        }
        slt[c * 64 + nl] = lt;
        srt[c * 64 + nl] = s - lt;    // t_dn = 1 - t_up
    }
    __syncthreads();

    // Phase 2: 4n x 4co x {M1,M2} register tiles.
    const int cg = tid & 15;          // co group (co0 = cg*4)
    const int ng = tid >> 4;          // n group  (n_l0 = ng*4)

    float4 a0 = {0,0,0,0}, a1 = {0,0,0,0}, a2 = {0,0,0,0}, a3 = {0,0,0,0};
    float4 b0 = {0,0,0,0}, b1 = {0,0,0,0}, b2 = {0,0,0,0}, b3 = {0,0,0,0};

#pragma unroll 16
    for (int c = 0; c < 64; c++) {
        float4 m1 = sM1[c * 16 + cg];
        float4 m2 = sM2[c * 16 + cg];
        float4 l = slt4[c * 16 + ng];
        float4 r = srt4[c * 16 + ng];

        a0.x = fmaf(l.x, m1.x, a0.x); a0.y = fmaf(l.x, m1.y, a0.y);
        a0.z = fmaf(l.x, m1.z, a0.z); a0.w = fmaf(l.x, m1.w, a0.w);
        a1.x = fmaf(l.y, m1.x, a1.x); a1.y = fmaf(l.y, m1.y, a1.y);
        a1.z = fmaf(l.y, m1.z, a1.z); a1.w = fmaf(l.y, m1.w, a1.w);
        a2.x = fmaf(l.z, m1.x, a2.x); a2.y = fmaf(l.z, m1.y, a2.y);
        a2.z = fmaf(l.z, m1.z, a2.z); a2.w = fmaf(l.z, m1.w, a2.w);
        a3.x = fmaf(l.w, m1.x, a3.x); a3.y = fmaf(l.w, m1.y, a3.y);
        a3.z = fmaf(l.w, m1.z, a3.z); a3.w = fmaf(l.w, m1.w, a3.w);

        b0.x = fmaf(r.x, m2.x, b0.x); b0.y = fmaf(r.x, m2.y, b0.y);
        b0.z = fmaf(r.x, m2.z, b0.z); b0.w = fmaf(r.x, m2.w, b0.w);
        b1.x = fmaf(r.y, m2.x, b1.x); b1.y = fmaf(r.y, m2.y, b1.y);
        b1.z = fmaf(r.y, m2.z, b1.z); b1.w = fmaf(r.y, m2.w, b1.w);
        b2.x = fmaf(r.z, m2.x, b2.x); b2.y = fmaf(r.z, m2.y, b2.y);
        b2.z = fmaf(r.z, m2.z, b2.z); b2.w = fmaf(r.z, m2.w, b2.w);
        b3.x = fmaf(r.w, m2.x, b3.x); b3.y = fmaf(r.w, m2.y, b3.y);
        b3.z = fmaf(r.w, m2.z, b3.z); b3.w = fmaf(r.w, m2.w, b3.w);
    }

    float4 cbv = reinterpret_cast<const float4*>(conv_b)[cg];
    float4* gA4 = reinterpret_cast<float4*>(g_A);
    float4* gB4 = reinterpret_cast<float4*>(g_Bv);

    const int g = cg >> 1;            // channel-group of 8
    const int h = cg & 1;             // half within group

    float4 av[4] = {a0, a1, a2, a3};
    float4 bv[4] = {b0, b1, b2, b3};
#pragma unroll
    for (int i = 0; i < 4; i++) {
        int n = n0 + ng * 4 + i;
        if (n < N_) {
            size_t o = ((size_t)(b * 8 + g) * N_ + n) * 2 + h;   // blocked layout
            float4 aa = av[i];
            aa.x += cbv.x; aa.y += cbv.y; aa.z += cbv.z; aa.w += cbv.w;
            gA4[o] = aa;
            gB4[o] = bv[i];
        }
    }
}

// ---------------------------------------------------------------------------
// Kernel 3: gather+add, smem-resident (b,g) table slices.
// Grid (chunk=2, g=8, b=8) = 128 blocks x 1024 threads (single wave).
// Each block stages its 64KB A-slice + 64KB B-slice into dynamic smem
// (XOR-swizzled to spread LDS.128 start banks), then streams 32000 edges.
// ---------------------------------------------------------------------------
#define ECHUNK 32000
#define NSLOT  (N_ * 2)     // 4000 float4 slots per slice

__device__ __forceinline__ int swz(int s) { return s ^ ((s >> 4) & 7); }

__global__ __launch_bounds__(1024) void gather_add_kernel(const int* __restrict__ idx,
                                                          const int* __restrict__ idy,
                                                          float4* __restrict__ out) {
    extern __shared__ float4 smem[];            // 2 * 4000 float4 = 128 KB
    float4* sA = smem;
    float4* sB = smem + NSLOT;

    const int ec = blockIdx.x;        // 0..1
    const int g  = blockIdx.y;        // 0..7
    const int b  = blockIdx.z;        // 0..7
    const int tid = threadIdx.x;

    const float4* __restrict__ Ag =
        reinterpret_cast<const float4*>(g_A) + (size_t)(b * 8 + g) * NSLOT;
    const float4* __restrict__ Bg =
        reinterpret_cast<const float4*>(g_Bv) + (size_t)(b * 8 + g) * NSLOT;

    // Stage slices into smem (coalesced global reads, swizzled smem writes)
#pragma unroll
    for (int k = 0; k < 4; k++) {
        int i = tid + 1024 * k;
        if (i < NSLOT) {
            sA[swz(i)] = Ag[i];
            sB[swz(i)] = Bg[i];
        }
    }
    __syncthreads();

    const int e0 = ec * ECHUNK;
    for (int i = tid; i < ECHUNK; i += 1024) {
        int e = e0 + i;
        int n1 = idx[e];
        int n2 = idy[e];
        int s1 = n1 * 2;
        int s2 = n2 * 2;
        int k1 = (s1 >> 4) & 7;       // same for s1 and s1+1 (s1 even)
        int k2 = (s2 >> 4) & 7;
        float4 a0 = sA[s1 ^ k1];
        float4 a1 = sA[(s1 + 1) ^ k1];
        float4 v0 = sB[s2 ^ k2];
        float4 v1 = sB[(s2 + 1) ^ k2];
        size_t o = ((size_t)b * E_ + e) * 16 + g * 2;
        out[o]     = make_float4(a0.x + v0.x, a0.y + v0.y, a0.z + v0.z, a0.w + v0.w);
        out[o + 1] = make_float4(a1.x + v1.x, a1.y + v1.y, a1.z + v1.z, a1.w + v1.w);
    }
}

// ---------------------------------------------------------------------------
// Launch. Inputs: x, idx, idy, W1_scale, W2_scale, W3, W4, conv_w, conv_b
// ---------------------------------------------------------------------------
extern "C" void kernel_launch(void* const* d_in, const int* in_sizes, int n_in,
                              void* d_out, int out_size) {
    const float* x   = (const float*)d_in[0];
    const int* idx   = (const int*)d_in[1];
    const int* idy   = (const int*)d_in[2];
    const float* s1  = (const float*)d_in[3];
    const float* s2  = (const float*)d_in[4];
    const float* W3  = (const float*)d_in[5];
    const float* W4  = (const float*)d_in[6];
    const float* cw  = (const float*)d_in[7];
    const float* cb  = (const float*)d_in[8];
    float4* out = (float4*)d_out;

    fold_M_kernel<<<16, 256>>>(W3, W4, cw, s1, s2);

    dim3 grd2((N_ + 63) / 64, B_);
    stage_AB_kernel<<<grd2, 256>>>(x, cb);

    const int smem_bytes = 2 * NSLOT * sizeof(float4);   // 128 KB
    static int configured = 0;
    if (!configured) {
        cudaFuncSetAttribute(gather_add_kernel,
                             cudaFuncAttributeMaxDynamicSharedMemorySize, smem_bytes);
        configured = 1;
    }
    dim3 grd3(E_ / ECHUNK, 8, B_);    // (2, 8, 8) = 128 blocks
    gather_add_kernel<<<grd3, 1024, smem_bytes>>>(idx, idy, out);
}

// round 6
// speedup vs baseline: 1.9565x; 1.5040x over previous
#include <cuda_runtime.h>
#include <cuda_fp16.h>
#include <cstdint>

// Problem shapes (fixed)
#define B_  8
#define C_  64
#define N_  2000
#define T_  12
#define E_  64000
#define HID_ 32

// Scratch
__device__ float g_M1[C_ * C_];            // M1[cin*64 + cout]
__device__ float g_M2[C_ * C_];
// fp16 tables, layout [b][n][64c] -> uint2 slot ((b*N+n)*16 + c4), 4 halves/slot
__device__ __half g_Ah[B_ * N_ * C_];      // includes conv_b
__device__ __half g_Bh[B_ * N_ * C_];

__device__ __forceinline__ unsigned pack_half2(float a, float b) {
    __half2 h = __floats2half2_rn(a, b);
    return *reinterpret_cast<unsigned*>(&h);
}

// ---------------------------------------------------------------------------
// Kernel 1: fold W3/W4 with conv_w and scales into 64x64 matrices.
// ---------------------------------------------------------------------------
__global__ __launch_bounds__(256) void fold_M_kernel(const float* __restrict__ W3,
                                                     const float* __restrict__ W4,
                                                     const float* __restrict__ cw,
                                                     const float* __restrict__ s1p,
                                                     const float* __restrict__ s2p) {
    __shared__ float cwt[64 * 65];   // cwt[h][cout], padded
    const int tid = threadIdx.x;

    for (int i = tid; i < 64 * 64; i += 256) {
        int cout = i >> 6;
        int h = i & 63;
        cwt[h * 65 + cout] = cw[i];
    }

    const int cout = tid & 63;
    const int cin = blockIdx.x * 4 + (tid >> 6);

    float w3r[HID_], w4r[HID_];
    const float4* p3 = reinterpret_cast<const float4*>(W3 + cin * HID_);
    const float4* p4 = reinterpret_cast<const float4*>(W4 + cin * HID_);
#pragma unroll
    for (int q = 0; q < 8; q++) {
        float4 v3 = p3[q], v4 = p4[q];
        w3r[q * 4 + 0] = v3.x; w3r[q * 4 + 1] = v3.y; w3r[q * 4 + 2] = v3.z; w3r[q * 4 + 3] = v3.w;
        w4r[q * 4 + 0] = v4.x; w4r[q * 4 + 1] = v4.y; w4r[q * 4 + 2] = v4.z; w4r[q * 4 + 3] = v4.w;
    }
    __syncthreads();

    float a = 0.f, b = 0.f;
#pragma unroll
    for (int h = 0; h < HID_; h++) {
        a = fmaf(w3r[h], cwt[h * 65 + cout], a);
        b = fmaf(w4r[h], cwt[(h + HID_) * 65 + cout], b);
    }
    g_M1[cin * 64 + cout] = a * s1p[0];
    g_M2[cin * 64 + cout] = b * s2p[0];
}

// ---------------------------------------------------------------------------
// Kernel 2: time reduction + 64x64 projection, 64-n tile per block.
// Identical math to R3; stores tables in fp16.
// ---------------------------------------------------------------------------
__global__ __launch_bounds__(256) void stage_AB_kernel(const float* __restrict__ x,
                                                       const float* __restrict__ conv_b) {
    __shared__ float4 sM1[64 * 16];    // [c][co/4]   16 KB
    __shared__ float4 sM2[64 * 16];    // 16 KB
    __shared__ float4 slt4[64 * 16];   // [c][n/4]    16 KB
    __shared__ float4 srt4[64 * 16];   // 16 KB
    float* sM1f = reinterpret_cast<float*>(sM1);
    float* sM2f = reinterpret_cast<float*>(sM2);
    float* slt = reinterpret_cast<float*>(slt4);
    float* srt = reinterpret_cast<float*>(srt4);

    const int tid = threadIdx.x;
    const int b = blockIdx.y;
    const int n0 = blockIdx.x * 64;

    for (int i = tid; i < 64 * 64; i += 256) {
        sM1f[i] = g_M1[i];
        sM2f[i] = g_M2[i];
    }

    // Phase 1: time reduction. 64c x 64n pairs, 16 per thread.
#pragma unroll
    for (int k = 0; k < 16; k++) {
        int p = tid + 256 * k;
        int c = p >> 6;
        int nl = p & 63;
        int n = n0 + nl;
        float lt = 0.f, s = 0.f;
        if (n < N_) {
            const float4* px = reinterpret_cast<const float4*>(
                x + ((size_t)(b * C_ + c) * N_ + n) * T_);
            float4 v0 = px[0], v1 = px[1], v2 = px[2];
            float xv[12] = {v0.x, v0.y, v0.z, v0.w,
                            v1.x, v1.y, v1.z, v1.w,
                            v2.x, v2.y, v2.z, v2.w};
#pragma unroll
            for (int t = 0; t < T_; t++) {
                lt = fmaf(xv[t], (float)t * (1.0f / 11.0f), lt);
                s += xv[t];
            }
        }
        slt[c * 64 + nl] = lt;
        srt[c * 64 + nl] = s - lt;    // t_dn = 1 - t_up
    }
    __syncthreads();

    // Phase 2: 4n x 4co x {M1,M2} register tiles.
    const int cg = tid & 15;          // co group (co0 = cg*4)
    const int ng = tid >> 4;          // n group  (n_l0 = ng*4)

    float4 a0 = {0,0,0,0}, a1 = {0,0,0,0}, a2 = {0,0,0,0}, a3 = {0,0,0,0};
    float4 b0 = {0,0,0,0}, b1 = {0,0,0,0}, b2 = {0,0,0,0}, b3 = {0,0,0,0};

#pragma unroll 16
    for (int c = 0; c < 64; c++) {
        float4 m1 = sM1[c * 16 + cg];
        float4 m2 = sM2[c * 16 + cg];
        float4 l = slt4[c * 16 + ng];
        float4 r = srt4[c * 16 + ng];

        a0.x = fmaf(l.x, m1.x, a0.x); a0.y = fmaf(l.x, m1.y, a0.y);
        a0.z = fmaf(l.x, m1.z, a0.z); a0.w = fmaf(l.x, m1.w, a0.w);
        a1.x = fmaf(l.y, m1.x, a1.x); a1.y = fmaf(l.y, m1.y, a1.y);
        a1.z = fmaf(l.y, m1.z, a1.z); a1.w = fmaf(l.y, m1.w, a1.w);
        a2.x = fmaf(l.z, m1.x, a2.x); a2.y = fmaf(l.z, m1.y, a2.y);
        a2.z = fmaf(l.z, m1.z, a2.z); a2.w = fmaf(l.z, m1.w, a2.w);
        a3.x = fmaf(l.w, m1.x, a3.x); a3.y = fmaf(l.w, m1.y, a3.y);
        a3.z = fmaf(l.w, m1.z, a3.z); a3.w = fmaf(l.w, m1.w, a3.w);

        b0.x = fmaf(r.x, m2.x, b0.x); b0.y = fmaf(r.x, m2.y, b0.y);
        b0.z = fmaf(r.x, m2.z, b0.z); b0.w = fmaf(r.x, m2.w, b0.w);
        b1.x = fmaf(r.y, m2.x, b1.x); b1.y = fmaf(r.y, m2.y, b1.y);
        b1.z = fmaf(r.y, m2.z, b1.z); b1.w = fmaf(r.y, m2.w, b1.w);
        b2.x = fmaf(r.z, m2.x, b2.x); b2.y = fmaf(r.z, m2.y, b2.y);
        b2.z = fmaf(r.z, m2.z, b2.z); b2.w = fmaf(r.z, m2.w, b2.w);
        b3.x = fmaf(r.w, m2.x, b3.x); b3.y = fmaf(r.w, m2.y, b3.y);
        b3.z = fmaf(r.w, m2.z, b3.z); b3.w = fmaf(r.w, m2.w, b3.w);
    }

    float4 cbv = reinterpret_cast<const float4*>(conv_b)[cg];
    uint2* gA2 = reinterpret_cast<uint2*>(g_Ah);
    uint2* gB2 = reinterpret_cast<uint2*>(g_Bh);

    float4 av[4] = {a0, a1, a2, a3};
    float4 bv[4] = {b0, b1, b2, b3};
#pragma unroll
    for (int i = 0; i < 4; i++) {
        int n = n0 + ng * 4 + i;
        if (n < N_) {
            size_t o = ((size_t)b * N_ + n) * 16 + cg;
            float4 aa = av[i];
            aa.x += cbv.x; aa.y += cbv.y; aa.z += cbv.z; aa.w += cbv.w;
            uint2 ua, ub;
            ua.x = pack_half2(aa.x, aa.y);
            ua.y = pack_half2(aa.z, aa.w);
            ub.x = pack_half2(bv[i].x, bv[i].y);
            ub.y = pack_half2(bv[i].z, bv[i].w);
            gA2[o] = ua;
            gB2[o] = ub;
        }
    }
}

// ---------------------------------------------------------------------------
// Kernel 3: out[b,e,c] = A[b,idx[e],c] + Bv[b,idy[e],c]  (fp16 tables, fp32 out)
// Grid (E/16, B), 256 threads: 16 edges/block, 16 threads (c-slice) per edge.
// Coalesced everywhere: 128B table row reads, 256B store per half-warp.
// ---------------------------------------------------------------------------
__global__ __launch_bounds__(256) void gather_add_kernel(const int* __restrict__ idx,
                                                         const int* __restrict__ idy,
                                                         float4* __restrict__ out) {
    __shared__ int sIdx[16], sIdy[16];
    const int tid = threadIdx.x;
    const int b = blockIdx.y;
    const int e0 = blockIdx.x * 16;

    if (tid < 16) sIdx[tid] = idx[e0 + tid];
    else if (tid < 32) sIdy[tid - 16] = idy[e0 + tid - 16];
    __syncthreads();

    const int c4 = tid & 15;
    const int el = tid >> 4;          // 0..15
    const int n1 = sIdx[el];
    const int n2 = sIdy[el];

    const uint2* __restrict__ A2 = reinterpret_cast<const uint2*>(g_Ah);
    const uint2* __restrict__ B2 = reinterpret_cast<const uint2*>(g_Bh);

    uint2 ua = __ldg(A2 + ((size_t)b * N_ + n1) * 16 + c4);
    uint2 ub = __ldg(B2 + ((size_t)b * N_ + n2) * 16 + c4);

    float2 a0 = __half22float2(*reinterpret_cast<__half2*>(&ua.x));
    float2 a1 = __half22float2(*reinterpret_cast<__half2*>(&ua.y));
    float2 v0 = __half22float2(*reinterpret_cast<__half2*>(&ub.x));
    float2 v1 = __half22float2(*reinterpret_cast<__half2*>(&ub.y));

    out[((size_t)b * E_ + e0 + el) * 16 + c4] =
        make_float4(a0.x + v0.x, a0.y + v0.y, a1.x + v1.x, a1.y + v1.y);
}

// ---------------------------------------------------------------------------
// Launch. Inputs: x, idx, idy, W1_scale, W2_scale, W3, W4, conv_w, conv_b
// ---------------------------------------------------------------------------
extern "C" void kernel_launch(void* const* d_in, const int* in_sizes, int n_in,
                              void* d_out, int out_size) {
    const float* x   = (const float*)d_in[0];
    const int* idx   = (const int*)d_in[1];
    const int* idy   = (const int*)d_in[2];
    const float* s1  = (const float*)d_in[3];
    const float* s2  = (const float*)d_in[4];
    const float* W3  = (const float*)d_in[5];
    const float* W4  = (const float*)d_in[6];
    const float* cw  = (const float*)d_in[7];
    const float* cb  = (const float*)d_in[8];
    float4* out = (float4*)d_out;

    fold_M_kernel<<<16, 256>>>(W3, W4, cw, s1, s2);

    dim3 grd2((N_ + 63) / 64, B_);
    stage_AB_kernel<<<grd2, 256>>>(x, cb);

    dim3 grd3(E_ / 16, B_);           // (4000, 8)
    gather_add_kernel<<<grd3, 256>>>(idx, idy, out);
}

// round 7
// speedup vs baseline: 2.4061x; 1.2298x over previous
#include <cuda_runtime.h>
#include <cuda_fp16.h>
#include <cstdint>

// Problem shapes (fixed)
#define B_  8
#define C_  64
#define N_  2000
#define T_  12
#define E_  64000
#define HID_ 32

// fp16 tables, layout [b][n][64c] -> uint2 slot ((b*N+n)*16 + c4), 4 halves/slot
__device__ __half g_Ah[B_ * N_ * C_];      // includes conv_b
__device__ __half g_Bh[B_ * N_ * C_];

__device__ __forceinline__ unsigned pack_half2(float a, float b) {
    __half2 h = __floats2half2_rn(a, b);
    return *reinterpret_cast<unsigned*>(&h);
}

// ---------------------------------------------------------------------------
// Stage kernel (fold eliminated via two-step GEMM):
//   slt/srt : time reduction of x                      (phase 1)
//   u = slt @ (s1*W3),  v = srt @ (s2*W4)              (phase 2a, 64x32)
//   A = u @ cw[:, :32]^T + cb,  Bv = v @ cw[:, 32:]^T   (phase 2b, 64x64)
// 64-n tile per block, 256 threads, 80 KB dynamic smem.
// ---------------------------------------------------------------------------
__global__ __launch_bounds__(256) void stage_AB_kernel(const float* __restrict__ x,
                                                       const float* __restrict__ W3,
                                                       const float* __restrict__ W4,
                                                       const float* __restrict__ cw,
                                                       const float* __restrict__ s1p,
                                                       const float* __restrict__ s2p,
                                                       const float* __restrict__ conv_b) {
    extern __shared__ float4 sm[];
    float4* sW3    = sm;            // [c][h4]   64*8  = 512 f4
    float4* sW4    = sm + 512;      // 512 f4
    float4* slt4   = sm + 1024;     // [c][n4]   64*16 = 1024 f4
    float4* srt4   = sm + 2048;     // 1024 f4
    float4* scwT1  = sm + 3072;     // [h][co4]  32*16 = 512 f4
    float4* scwT2  = sm + 3584;     // 512 f4
    float4* su4    = sm + 4096;     // [h][n4]   32*16 = 512 f4
    float4* sv4    = sm + 4608;     // 512 f4
    float* slt = reinterpret_cast<float*>(slt4);
    float* srt = reinterpret_cast<float*>(srt4);
    float* scwT1f = reinterpret_cast<float*>(scwT1);
    float* scwT2f = reinterpret_cast<float*>(scwT2);

    const int tid = threadIdx.x;
    const int b = blockIdx.y;
    const int n0 = blockIdx.x * 64;

    const float s1 = __ldg(s1p);
    const float s2 = __ldg(s2p);

    // Stage scaled W3/W4 (each 512 f4)
    const float4* W3_4 = reinterpret_cast<const float4*>(W3);
    const float4* W4_4 = reinterpret_cast<const float4*>(W4);
#pragma unroll
    for (int k = 0; k < 2; k++) {
        int i = tid + 256 * k;
        float4 w3 = W3_4[i], w4 = W4_4[i];
        sW3[i] = make_float4(w3.x * s1, w3.y * s1, w3.z * s1, w3.w * s1);
        sW4[i] = make_float4(w4.x * s2, w4.y * s2, w4.z * s2, w4.w * s2);
    }

    // Stage cw transposed: scwT1[h][co] = cw[co][h], scwT2[h][co] = cw[co][32+h]
    // (strided global reads; cw is 16KB and L2-hot; smem writes contiguous)
#pragma unroll
    for (int k = 0; k < 16; k++) {
        int id = tid + 256 * k;     // 0..4095
        int co = id & 63;
        int hh = id >> 6;           // 0..63
        float vv = __ldg(cw + co * 64 + hh);
        if (hh < 32) scwT1f[hh * 64 + co] = vv;
        else         scwT2f[(hh - 32) * 64 + co] = vv;
    }

    // Phase 1: time reduction. 64c x 64n pairs, 16 per thread.
#pragma unroll
    for (int k = 0; k < 16; k++) {
        int p = tid + 256 * k;
        int c = p >> 6;
        int nl = p & 63;
        int n = n0 + nl;
        float lt = 0.f, s = 0.f;
        if (n < N_) {
            const float4* px = reinterpret_cast<const float4*>(
                x + ((size_t)(b * C_ + c) * N_ + n) * T_);
            float4 v0 = px[0], v1 = px[1], v2 = px[2];
            float xv[12] = {v0.x, v0.y, v0.z, v0.w,
                            v1.x, v1.y, v1.z, v1.w,
                            v2.x, v2.y, v2.z, v2.w};
#pragma unroll
            for (int t = 0; t < T_; t++) {
                lt = fmaf(xv[t], (float)t * (1.0f / 11.0f), lt);
                s += xv[t];
            }
        }
        slt[c * 64 + nl] = lt;
        srt[c * 64 + nl] = s - lt;    // t_dn = 1 - t_up
    }
    __syncthreads();

    // Phase 2a: u[h][n] = sum_c slt[c][n]*sW3[c][h]  (threads 0..127)
    //           v[h][n] = sum_c srt[c][n]*sW4[c][h]  (threads 128..255)
    {
        const int t = tid & 127;
        const int ng2 = t & 15;       // n4 group
        const int hg = t >> 4;        // 0..7 (h4 group)
        const float4* src = (tid < 128) ? slt4 : srt4;
        const float4* wsm = (tid < 128) ? sW3 : sW4;
        float4* dst = (tid < 128) ? su4 : sv4;

        float4 acc0 = {0,0,0,0}, acc1 = {0,0,0,0}, acc2 = {0,0,0,0}, acc3 = {0,0,0,0};
#pragma unroll 16
        for (int c = 0; c < 64; c++) {
            float4 l4 = src[c * 16 + ng2];
            float4 w = wsm[c * 8 + hg];
            acc0.x = fmaf(l4.x, w.x, acc0.x); acc0.y = fmaf(l4.y, w.x, acc0.y);
            acc0.z = fmaf(l4.z, w.x, acc0.z); acc0.w = fmaf(l4.w, w.x, acc0.w);
            acc1.x = fmaf(l4.x, w.y, acc1.x); acc1.y = fmaf(l4.y, w.y, acc1.y);
            acc1.z = fmaf(l4.z, w.y, acc1.z); acc1.w = fmaf(l4.w, w.y, acc1.w);
            acc2.x = fmaf(l4.x, w.z, acc2.x); acc2.y = fmaf(l4.y, w.z, acc2.y);
            acc2.z = fmaf(l4.z, w.z, acc2.z); acc2.w = fmaf(l4.w, w.z, acc2.w);
            acc3.x = fmaf(l4.x, w.w, acc3.x); acc3.y = fmaf(l4.y, w.w, acc3.y);
            acc3.z = fmaf(l4.z, w.w, acc3.z); acc3.w = fmaf(l4.w, w.w, acc3.w);
        }
        dst[(hg * 4 + 0) * 16 + ng2] = acc0;
        dst[(hg * 4 + 1) * 16 + ng2] = acc1;
        dst[(hg * 4 + 2) * 16 + ng2] = acc2;
        dst[(hg * 4 + 3) * 16 + ng2] = acc3;
    }
    __syncthreads();

    // Phase 2b: A[n][co] = sum_h u[h][n]*scwT1[h][co] (+cb); Bv from v, scwT2.
    const int cg = tid & 15;          // co4 group
    const int ng = tid >> 4;          // n4 group

    float4 a0 = {0,0,0,0}, a1 = {0,0,0,0}, a2 = {0,0,0,0}, a3 = {0,0,0,0};
    float4 b0 = {0,0,0,0}, b1 = {0,0,0,0}, b2 = {0,0,0,0}, b3 = {0,0,0,0};

#pragma unroll 8
    for (int h = 0; h < 32; h++) {
        float4 u4 = su4[h * 16 + ng];
        float4 v4 = sv4[h * 16 + ng];
        float4 m1 = scwT1[h * 16 + cg];
        float4 m2 = scwT2[h * 16 + cg];

        a0.x = fmaf(u4.x, m1.x, a0.x); a0.y = fmaf(u4.x, m1.y, a0.y);
        a0.z = fmaf(u4.x, m1.z, a0.z); a0.w = fmaf(u4.x, m1.w, a0.w);
        a1.x = fmaf(u4.y, m1.x, a1.x); a1.y = fmaf(u4.y, m1.y, a1.y);
        a1.z = fmaf(u4.y, m1.z, a1.z); a1.w = fmaf(u4.y, m1.w, a1.w);
        a2.x = fmaf(u4.z, m1.x, a2.x); a2.y = fmaf(u4.z, m1.y, a2.y);
        a2.z = fmaf(u4.z, m1.z, a2.z); a2.w = fmaf(u4.z, m1.w, a2.w);
        a3.x = fmaf(u4.w, m1.x, a3.x); a3.y = fmaf(u4.w, m1.y, a3.y);
        a3.z = fmaf(u4.w, m1.z, a3.z); a3.w = fmaf(u4.w, m1.w, a3.w);

        b0.x = fmaf(v4.x, m2.x, b0.x); b0.y = fmaf(v4.x, m2.y, b0.y);
        b0.z = fmaf(v4.x, m2.z, b0.z); b0.w = fmaf(v4.x, m2.w, b0.w);
        b1.x = fmaf(v4.y, m2.x, b1.x); b1.y = fmaf(v4.y, m2.y, b1.y);
        b1.z = fmaf(v4.y, m2.z, b1.z); b1.w = fmaf(v4.y, m2.w, b1.w);
        b2.x = fmaf(v4.z, m2.x, b2.x); b2.y = fmaf(v4.z, m2.y, b2.y);
        b2.z = fmaf(v4.z, m2.z, b2.z); b2.w = fmaf(v4.z, m2.w, b2.w);
        b3.x = fmaf(v4.w, m2.x, b3.x); b3.y = fmaf(v4.w, m2.y, b3.y);
        b3.z = fmaf(v4.w, m2.z, b3.z); b3.w = fmaf(v4.w, m2.w, b3.w);
    }

    float4 cbv = reinterpret_cast<const float4*>(conv_b)[cg];
    uint2* gA2 = reinterpret_cast<uint2*>(g_Ah);
    uint2* gB2 = reinterpret_cast<uint2*>(g_Bh);

    float4 av[4] = {a0, a1, a2, a3};
    float4 bv[4] = {b0, b1, b2, b3};
#pragma unroll
    for (int i = 0; i < 4; i++) {
        int n = n0 + ng * 4 + i;
        if (n < N_) {
            size_t o = ((size_t)b * N_ + n) * 16 + cg;
            float4 aa = av[i];
            aa.x += cbv.x; aa.y += cbv.y; aa.z += cbv.z; aa.w += cbv.w;
            uint2 ua, ub;
            ua.x = pack_half2(aa.x, aa.y);
            ua.y = pack_half2(aa.z, aa.w);
            ub.x = pack_half2(bv[i].x, bv[i].y);
            ub.y = pack_half2(bv[i].z, bv[i].w);
            gA2[o] = ua;
            gB2[o] = ub;
        }
    }
}

// ---------------------------------------------------------------------------
// Gather kernel: out[b,e,c] = A[b,idx[e],c] + Bv[b,idy[e],c]
// Grid (E/32, 2 channel-halves, B). Channel-half partition shrinks the
// per-block gather working set to ~256 KB (A+B half-rows) for L1 residency.
// 8 threads per edge (uint2 = 4 halves each).
// ---------------------------------------------------------------------------
__global__ __launch_bounds__(256) void gather_add_kernel(const int* __restrict__ idx,
                                                         const int* __restrict__ idy,
                                                         float4* __restrict__ out) {
    const int tid = threadIdx.x;
    const int chalf = blockIdx.y;     // 0..1
    const int b = blockIdx.z;         // 0..7
    const int el = tid >> 3;          // 0..31
    const int q = tid & 7;            // uint2 within 64B half-row
    const int e = blockIdx.x * 32 + el;

    const int n1 = __ldg(idx + e);
    const int n2 = __ldg(idy + e);

    const uint2* __restrict__ A2 = reinterpret_cast<const uint2*>(g_Ah);
    const uint2* __restrict__ B2 = reinterpret_cast<const uint2*>(g_Bh);

    const int cq = chalf * 8 + q;
    uint2 ua = __ldg(A2 + ((size_t)b * N_ + n1) * 16 + cq);
    uint2 ub = __ldg(B2 + ((size_t)b * N_ + n2) * 16 + cq);

    float2 a0 = __half22float2(*reinterpret_cast<__half2*>(&ua.x));
    float2 a1 = __half22float2(*reinterpret_cast<__half2*>(&ua.y));
    float2 v0 = __half22float2(*reinterpret_cast<__half2*>(&ub.x));
    float2 v1 = __half22float2(*reinterpret_cast<__half2*>(&ub.y));

    out[((size_t)b * E_ + e) * 16 + cq] =
        make_float4(a0.x + v0.x, a0.y + v0.y, a1.x + v1.x, a1.y + v1.y);
}

// ---------------------------------------------------------------------------
// Launch. Inputs: x, idx, idy, W1_scale, W2_scale, W3, W4, conv_w, conv_b
// ---------------------------------------------------------------------------
extern "C" void kernel_launch(void* const* d_in, const int* in_sizes, int n_in,
                              void* d_out, int out_size) {
    const float* x   = (const float*)d_in[0];
    const int* idx   = (const int*)d_in[1];
    const int* idy   = (const int*)d_in[2];
    const float* s1  = (const float*)d_in[3];
    const float* s2  = (const float*)d_in[4];
    const float* W3  = (const float*)d_in[5];
    const float* W4  = (const float*)d_in[6];
    const float* cw  = (const float*)d_in[7];
    const float* cb  = (const float*)d_in[8];
    float4* out = (float4*)d_out;

    const int smem_bytes = 5120 * sizeof(float4);   // 80 KB
    cudaFuncSetAttribute(stage_AB_kernel,
                         cudaFuncAttributeMaxDynamicSharedMemorySize, smem_bytes);

    dim3 grd2((N_ + 63) / 64, B_);
    stage_AB_kernel<<<grd2, 256, smem_bytes>>>(x, W3, W4, cw, s1, s2, cb);

    dim3 grd3(E_ / 32, 2, B_);        // (2000, 2, 8)
    gather_add_kernel<<<grd3, 256>>>(idx, idy, out);
}